// round 1
// baseline (speedup 1.0000x reference)
#include <cuda_runtime.h>
#include <utility>

#define DH __host__ __device__

// ---------------- compile-time Clebsch-Gordan machinery ----------------

DH constexpr int cabsi(int a) { return a < 0 ? -a : a; }
DH constexpr int cmini(int a, int b) { return a < b ? a : b; }

DH constexpr double cfact(int n) {
    double r = 1.0;
    for (int i = 2; i <= n; ++i) r *= (double)i;
    return r;
}

// constexpr sqrt via Newton iteration (portable: std::sqrt is not constexpr in C++17)
DH constexpr double csqrt(double x) {
    if (x <= 0.0) return 0.0;
    double g = x < 1.0 ? 1.0 : x;
    for (int i = 0; i < 200; ++i) g = 0.5 * (g + x / g);
    return g;
}

// Condon-Shortley CG coefficient <j1 m1 j2 m2 | j3 m3> (Racah formula),
// exact mirror of the reference implementation, evaluated at COMPILE TIME.
DH constexpr double cg_coef(int j1, int m1, int j2, int m2, int j3, int m3) {
    if (m1 + m2 != m3) return 0.0;
    if (j3 < cabsi(j1 - j2) || j3 > j1 + j2) return 0.0;
    double pref = csqrt((2.0 * j3 + 1.0) * cfact(j3 + j1 - j2) * cfact(j3 - j1 + j2)
                        * cfact(j1 + j2 - j3) / cfact(j1 + j2 + j3 + 1));
    pref *= csqrt(cfact(j3 + m3) * cfact(j3 - m3) * cfact(j1 - m1) * cfact(j1 + m1)
                  * cfact(j2 - m2) * cfact(j2 + m2));
    double s = 0.0;
    for (int k = 0; k <= j1 + j2 - j3; ++k) {
        int a2 = j1 + j2 - j3 - k, a3 = j1 - m1 - k, a4 = j2 + m2 - k;
        int a5 = j3 - j2 + m1 + k, a6 = j3 - j1 - m2 + k;
        if (a2 < 0 || a3 < 0 || a4 < 0 || a5 < 0 || a6 < 0) continue;
        double den = cfact(k) * cfact(a2) * cfact(a3) * cfact(a4) * cfact(a5) * cfact(a6);
        s += ((k & 1) ? -1.0 : 1.0) / den;
    }
    return pref * s;
}

// ---------------- problem geometry (compile-time) ----------------

constexpr int TOTAL_IN = 2304;       // floats per batch row
constexpr long OUT_POS = 789504;     // float2 (re,im) positions per batch row

DH constexpr bool tvalid(int l, int l1, int l2) {
    return cabsi(l1 - l2) <= l && l <= l1 + l2;
}
DH constexpr int ntup(int l) {
    int c = 0;
    for (int l1 = 0; l1 <= 5; ++l1)
        for (int l2 = 0; l2 <= 5; ++l2)
            if (tvalid(l, l1, l2)) ++c;
    return c;
}
// base (in float2 positions) of output degree l within one batch row
DH constexpr long outbase(int l) {
    long s = 0;
    for (int lp = 0; lp < l; ++lp) s += (long)ntup(lp) * 1024 * (2 * lp + 1);
    return s;
}
// rank of pair (L1,L2) among valid tuples of degree l (lexicographic l1-major)
DH constexpr int pair_rank(int l, int L1, int L2) {
    int r = 0;
    for (int l1 = 0; l1 <= 5; ++l1)
        for (int l2 = 0; l2 <= 5; ++l2)
            if ((l1 < L1 || (l1 == L1 && l2 < L2)) && tvalid(l, l1, l2)) ++r;
    return r;
}

// ---------------- static_for helper ----------------

template <class F, int... Is>
__device__ __forceinline__ void sfor_impl(F&& f, std::integer_sequence<int, Is...>) {
    (f(std::integral_constant<int, Is>{}), ...);
}
template <int N, class F>
__device__ __forceinline__ void sfor(F&& f) {
    sfor_impl(f, std::make_integer_sequence<int, N>{});
}

// ---------------- per-pair fully-unrolled worker ----------------
//
// One thread handles one (batch b, t = t1*32+t2) for pair (L1,L2):
//   products a[m1]*b[m2] (complex, 4 FMA-pipe instrs) computed once, then
//   accumulated into every valid output degree l with the CG coefficient as
//   an IMMEDIATE (FFMA-imm, rt_SMSP=1). All indices compile-time -> acc[] in regs.

template <int L1, int L2>
__device__ __forceinline__ void do_pair(const float* __restrict__ fs,
                                        float2* __restrict__ out, int b, int t) {
    constexpr int M1 = 2 * L1 + 1;
    constexpr int M2 = 2 * L2 + 1;
    constexpr int LMIN = (L1 > L2) ? (L1 - L2) : (L2 - L1);
    constexpr int LMX = cmini(5, L1 + L2);
    constexpr int NL = LMX - LMIN + 1;
    constexpr int NACC = (LMX + 1) * (LMX + 1) - LMIN * LMIN;  // sum of (2l+1)

    float2 acc[NACC];
#pragma unroll
    for (int i = 0; i < NACC; ++i) acc[i] = make_float2(0.f, 0.f);

    const int t1 = t >> 5;
    const int t2 = t & 31;

    // input fragment l starts at 64*l*l floats; row for tau is contiguous (2l+1)*2 floats
    const float2* __restrict__ arow =
        reinterpret_cast<const float2*>(fs + (long)b * TOTAL_IN + 64 * L1 * L1 + t1 * M1 * 2);
    const float2* __restrict__ brow =
        reinterpret_cast<const float2*>(fs + (long)b * TOTAL_IN + 64 * L2 * L2 + t2 * M2 * 2);

    float2 bv[M2];
#pragma unroll
    for (int i = 0; i < M2; ++i) bv[i] = brow[i];

    sfor<M1>([&](auto I1) {
        constexpr int im1 = decltype(I1)::value;
        const float2 av = arow[im1];  // warp-uniform (t1 constant per warp) -> broadcast
        sfor<M2>([&](auto I2) {
            constexpr int im2 = decltype(I2)::value;
            constexpr int m = (im1 - L1) + (im2 - L2);
            if constexpr (m >= -LMX && m <= LMX) {
                const float pr = av.x * bv[im2].x - av.y * bv[im2].y;
                const float pi = av.x * bv[im2].y + av.y * bv[im2].x;
                sfor<NL>([&](auto J) {
                    constexpr int l = LMIN + decltype(J)::value;
                    if constexpr (m >= -l && m <= l) {
                        constexpr float c =
                            (float)cg_coef(L1, im1 - L1, L2, im2 - L2, l, m);
                        if constexpr (c != 0.0f) {
                            constexpr int ao = (l * l - LMIN * LMIN) + (m + l);
                            acc[ao].x += c * pr;   // FFMA with immediate multiplier
                            acc[ao].y += c * pi;
                        }
                    }
                });
            }
        });
    });

    // write results: per degree l, (2l+1) contiguous float2 at
    // b*OUT_POS + outbase(l) + rank*1024*(2l+1) + t*(2l+1)
    const long obatch = (long)b * OUT_POS;
    sfor<NL>([&](auto J) {
        constexpr int l = LMIN + decltype(J)::value;
        constexpr long pbase = outbase(l) + (long)pair_rank(l, L1, L2) * 1024 * (2 * l + 1);
        float2* __restrict__ o = out + obatch + pbase + (long)t * (2 * l + 1);
#pragma unroll
        for (int mm = 0; mm < 2 * l + 1; ++mm)
            o[mm] = acc[(l * l - LMIN * LMIN) + mm];
    });
}

// ---------------- kernel: 36 pairs x 32 batches x 1024 t, 256 thr/blk ----------------

__global__ void __launch_bounds__(256)
cg_kernel(const float* __restrict__ fs, float2* __restrict__ out) {
    const int bid = blockIdx.x;
    const int pair = 35 - (bid >> 7);  // heavy pairs (large l1+l2) scheduled first
    const int r = bid & 127;           // 32 batches * 4 t-tiles
    const int b = r >> 2;
    const int t = ((r & 3) << 8) + threadIdx.x;

#define PC(P) case P: do_pair<(P) / 6, (P) % 6>(fs, out, b, t); break;
    switch (pair) {
        PC(0)  PC(1)  PC(2)  PC(3)  PC(4)  PC(5)
        PC(6)  PC(7)  PC(8)  PC(9)  PC(10) PC(11)
        PC(12) PC(13) PC(14) PC(15) PC(16) PC(17)
        PC(18) PC(19) PC(20) PC(21) PC(22) PC(23)
        PC(24) PC(25) PC(26) PC(27) PC(28) PC(29)
        PC(30) PC(31) PC(32) PC(33) PC(34) PC(35)
        default: break;
    }
#undef PC
}

extern "C" void kernel_launch(void* const* d_in, const int* in_sizes, int n_in,
                              void* d_out, int out_size) {
    const float* fs = (const float*)d_in[0];
    float2* out = (float2*)d_out;
    // 36 pairs * 32 batches * 4 tiles = 4608 blocks, 256 threads each:
    // exactly one thread per (pair, batch, t) work item.
    cg_kernel<<<4608, 256>>>(fs, out);
}

// round 2
// speedup vs baseline: 1.7950x; 1.7950x over previous
#include <cuda_runtime.h>
#include <utility>

#define DH __host__ __device__

// ---------------- compile-time Clebsch-Gordan machinery ----------------

DH constexpr int cabsi(int a) { return a < 0 ? -a : a; }
DH constexpr int cmini(int a, int b) { return a < b ? a : b; }

DH constexpr double cfact(int n) {
    double r = 1.0;
    for (int i = 2; i <= n; ++i) r *= (double)i;
    return r;
}

DH constexpr double csqrt(double x) {
    if (x <= 0.0) return 0.0;
    double g = x < 1.0 ? 1.0 : x;
    for (int i = 0; i < 200; ++i) g = 0.5 * (g + x / g);
    return g;
}

// Condon-Shortley CG coefficient (Racah formula), compile-time, mirrors reference.
DH constexpr double cg_coef(int j1, int m1, int j2, int m2, int j3, int m3) {
    if (m1 + m2 != m3) return 0.0;
    if (j3 < cabsi(j1 - j2) || j3 > j1 + j2) return 0.0;
    double pref = csqrt((2.0 * j3 + 1.0) * cfact(j3 + j1 - j2) * cfact(j3 - j1 + j2)
                        * cfact(j1 + j2 - j3) / cfact(j1 + j2 + j3 + 1));
    pref *= csqrt(cfact(j3 + m3) * cfact(j3 - m3) * cfact(j1 - m1) * cfact(j1 + m1)
                  * cfact(j2 - m2) * cfact(j2 + m2));
    double s = 0.0;
    for (int k = 0; k <= j1 + j2 - j3; ++k) {
        int a2 = j1 + j2 - j3 - k, a3 = j1 - m1 - k, a4 = j2 + m2 - k;
        int a5 = j3 - j2 + m1 + k, a6 = j3 - j1 - m2 + k;
        if (a2 < 0 || a3 < 0 || a4 < 0 || a5 < 0 || a6 < 0) continue;
        double den = cfact(k) * cfact(a2) * cfact(a3) * cfact(a4) * cfact(a5) * cfact(a6);
        s += ((k & 1) ? -1.0 : 1.0) / den;
    }
    return pref * s;
}

// ---------------- problem geometry (compile-time) ----------------

constexpr int TOTAL_IN = 2304;       // floats per batch row
constexpr long OUT_POS = 789504;     // float2 (re,im) positions per batch row

DH constexpr bool tvalid(int l, int l1, int l2) {
    return cabsi(l1 - l2) <= l && l <= l1 + l2;
}
DH constexpr int ntup(int l) {
    int c = 0;
    for (int l1 = 0; l1 <= 5; ++l1)
        for (int l2 = 0; l2 <= 5; ++l2)
            if (tvalid(l, l1, l2)) ++c;
    return c;
}
DH constexpr long outbase(int l) {
    long s = 0;
    for (int lp = 0; lp < l; ++lp) s += (long)ntup(lp) * 1024 * (2 * lp + 1);
    return s;
}
DH constexpr int pair_rank(int l, int L1, int L2) {
    int r = 0;
    for (int l1 = 0; l1 <= 5; ++l1)
        for (int l2 = 0; l2 <= 5; ++l2)
            if ((l1 < L1 || (l1 == L1 && l2 < L2)) && tvalid(l, l1, l2)) ++r;
    return r;
}

// ---------------- static_for helper ----------------

template <class F, int... Is>
__device__ __forceinline__ void sfor_impl(F&& f, std::integer_sequence<int, Is...>) {
    (f(std::integral_constant<int, Is>{}), ...);
}
template <int N, class F>
__device__ __forceinline__ void sfor(F&& f) {
    sfor_impl(f, std::make_integer_sequence<int, N>{});
}

// per-warp shared staging: 32 t-values x up to 11 float2 = 352 float2 = 2816 B
constexpr int STAGE_F2 = 32 * 11;

// ---------------- per-pair fully-unrolled worker ----------------

template <int L1, int L2>
__device__ __forceinline__ void do_pair(const float* __restrict__ fs,
                                        float2* __restrict__ out,
                                        float2* __restrict__ ws,  // this warp's stage
                                        int b, int t) {
    constexpr int M1 = 2 * L1 + 1;
    constexpr int M2 = 2 * L2 + 1;
    constexpr int LMIN = (L1 > L2) ? (L1 - L2) : (L2 - L1);
    constexpr int LMX = cmini(5, L1 + L2);
    constexpr int NL = LMX - LMIN + 1;
    constexpr int NACC = (LMX + 1) * (LMX + 1) - LMIN * LMIN;

    float2 acc[NACC];
#pragma unroll
    for (int i = 0; i < NACC; ++i) acc[i] = make_float2(0.f, 0.f);

    const int t1 = t >> 5;
    const int t2 = t & 31;  // == lane id

    const float2* __restrict__ arow =
        reinterpret_cast<const float2*>(fs + (long)b * TOTAL_IN + 64 * L1 * L1 + t1 * M1 * 2);
    const float2* __restrict__ brow =
        reinterpret_cast<const float2*>(fs + (long)b * TOTAL_IN + 64 * L2 * L2 + t2 * M2 * 2);

    float2 bv[M2];
#pragma unroll
    for (int i = 0; i < M2; ++i) bv[i] = brow[i];

    sfor<M1>([&](auto I1) {
        constexpr int im1 = decltype(I1)::value;
        const float2 av = arow[im1];  // warp-uniform broadcast
        sfor<M2>([&](auto I2) {
            constexpr int im2 = decltype(I2)::value;
            constexpr int m = (im1 - L1) + (im2 - L2);
            if constexpr (m >= -LMX && m <= LMX) {
                const float pr = av.x * bv[im2].x - av.y * bv[im2].y;
                const float pi = av.x * bv[im2].y + av.y * bv[im2].x;
                sfor<NL>([&](auto J) {
                    constexpr int l = LMIN + decltype(J)::value;
                    if constexpr (m >= -l && m <= l) {
                        constexpr float c =
                            (float)cg_coef(L1, im1 - L1, L2, im2 - L2, l, m);
                        if constexpr (c != 0.0f) {
                            constexpr int ao = (l * l - LMIN * LMIN) + (m + l);
                            acc[ao].x += c * pr;  // FFMA-imm
                            acc[ao].y += c * pi;
                        }
                    }
                });
            }
        });
    });

    // ---- writeback: smem transpose -> fully coalesced 128-bit stores ----
    // For each degree l the warp owns a CONTIGUOUS gmem region of
    // 32*(2l+1) float2 starting at tile base (t & ~31)*(2l+1).
    const long obatch = (long)b * OUT_POS;
    sfor<NL>([&](auto J) {
        constexpr int l = LMIN + decltype(J)::value;
        constexpr int NM = 2 * l + 1;
        constexpr long pbase = outbase(l) + (long)pair_rank(l, L1, L2) * 1024 * NM;

        __syncwarp();
#pragma unroll
        for (int mm = 0; mm < NM; ++mm)
            ws[t2 * NM + mm] = acc[(l * l - LMIN * LMIN) + mm];
        __syncwarp();

        // copy 32*NM float2 = 16*NM float4, coalesced
        const float4* __restrict__ s4 = reinterpret_cast<const float4*>(ws);
        float4* __restrict__ o4 = reinterpret_cast<float4*>(
            out + obatch + pbase + (long)(t & ~31) * NM);
        constexpr int CNT4 = 16 * NM;
#pragma unroll
        for (int i = 0; i < (CNT4 + 31) / 32; ++i) {
            const int idx = i * 32 + t2;
            if (CNT4 % 32 == 0 || idx < CNT4) o4[idx] = s4[idx];
        }
    });
}

// ---------------- kernel: 36 pairs x 32 batches x 4 t-tiles, 256 thr/blk ----------------

__global__ void __launch_bounds__(256)
cg_kernel(const float* __restrict__ fs, float2* __restrict__ out) {
    __shared__ float2 stage[8][STAGE_F2];

    const int bid = blockIdx.x;
    const int pair = 35 - (bid >> 7);  // heavy pairs first
    const int r = bid & 127;
    const int b = r >> 2;
    const int t = ((r & 3) << 8) + threadIdx.x;
    float2* ws = stage[threadIdx.x >> 5];

#define PC(P) case P: do_pair<(P) / 6, (P) % 6>(fs, out, ws, b, t); break;
    switch (pair) {
        PC(0)  PC(1)  PC(2)  PC(3)  PC(4)  PC(5)
        PC(6)  PC(7)  PC(8)  PC(9)  PC(10) PC(11)
        PC(12) PC(13) PC(14) PC(15) PC(16) PC(17)
        PC(18) PC(19) PC(20) PC(21) PC(22) PC(23)
        PC(24) PC(25) PC(26) PC(27) PC(28) PC(29)
        PC(30) PC(31) PC(32) PC(33) PC(34) PC(35)
        default: break;
    }
#undef PC
}

extern "C" void kernel_launch(void* const* d_in, const int* in_sizes, int n_in,
                              void* d_out, int out_size) {
    const float* fs = (const float*)d_in[0];
    float2* out = (float2*)d_out;
    cg_kernel<<<4608, 256>>>(fs, out);
}